// round 3
// baseline (speedup 1.0000x reference)
#include <cuda_runtime.h>
#include <math.h>

#define N_NODES 8192
#define NFEAT   256
#define NHID    64
#define NHEADS  4
#define DHID    (NHEADS*NHID)   /* 256 */
#define NCLASS  121
#define LDC2    128             /* padded ld for Whc */
#define MAXDEG  512
#define LRELU_ALPHA 0.2f

/* ---------------- scratch (static device globals; no allocs) -------------- */
__device__ float g_Wh[N_NODES * DHID];        /* 8 MB  layer-1 Wh, heads concat */
__device__ float g_Wcat[NFEAT * DHID];        /* 256 KB packed W */
__device__ float g_wa[8][NFEAT];              /* W@a projected vecs: [0..3]=src h, [4..7]=dst h */
__device__ float g_fs[NHEADS * N_NODES];
__device__ float g_fd[NHEADS * N_NODES];
__device__ float g_hcat[N_NODES * DHID];      /* 8 MB layer-1 output */
__device__ float g_Whc[N_NODES * LDC2];       /* 4 MB layer-2 Wh (ld=128) */
__device__ float g_v2s[DHID];
__device__ float g_v2d[DHID];
__device__ float g_f2s[N_NODES];
__device__ float g_f2d[N_NODES];
__device__ int   g_cols[(size_t)N_NODES * MAXDEG];  /* 16 MB edge lists */
__device__ int   g_deg[N_NODES];

/* ---------------- 1. build per-row edge lists (one pass over adj) --------- */
__global__ void build_edges(const float* __restrict__ adj) {
    int row = blockIdx.x;
    int tid = threadIdx.x;
    const float4* a4 = (const float4*)(adj + (size_t)row * N_NODES + tid * 32);

    float4 v[8];
    int cnt = 0;
#pragma unroll
    for (int q = 0; q < 8; q++) {
        v[q] = a4[q];
        cnt += (v[q].x > 0.f) + (v[q].y > 0.f) + (v[q].z > 0.f) + (v[q].w > 0.f);
    }

    __shared__ int s[256];
    s[tid] = cnt;
    __syncthreads();
    for (int off = 1; off < 256; off <<= 1) {
        int t = (tid >= off) ? s[tid - off] : 0;
        __syncthreads();
        s[tid] += t;
        __syncthreads();
    }
    int pos = s[tid] - cnt;            /* exclusive prefix */
    if (tid == 0) {
        int total = s[255];
        g_deg[row] = total < MAXDEG ? total : MAXDEG;
    }

    int* outc = g_cols + (size_t)row * MAXDEG;
#pragma unroll
    for (int q = 0; q < 8; q++) {
        int base = tid * 32 + q * 4;
        if (v[q].x > 0.f) { if (pos < MAXDEG) outc[pos] = base + 0; pos++; }
        if (v[q].y > 0.f) { if (pos < MAXDEG) outc[pos] = base + 1; pos++; }
        if (v[q].z > 0.f) { if (pos < MAXDEG) outc[pos] = base + 2; pos++; }
        if (v[q].w > 0.f) { if (pos < MAXDEG) outc[pos] = base + 3; pos++; }
    }
}

/* ---------------- 2. pack Ws [H,256,64] -> Wcat [256,256] ----------------- */
__global__ void pack_W(const float* __restrict__ Ws) {
    int idx = blockIdx.x * blockDim.x + threadIdx.x;
    int n = idx & 255;
    int k = idx >> 8;
    int h = n >> 6, c = n & 63;
    g_Wcat[k * DHID + n] = Ws[((size_t)h * NFEAT + k) * NHID + c];
}

/* ---------------- 2b. wa[i][k] = sum_c Ws[h][k][c]*a[h][sd*64+c] ---------- */
__global__ void prep_wa(const float* __restrict__ Ws, const float* __restrict__ a_heads) {
    int idx = blockIdx.x * blockDim.x + threadIdx.x;   /* 2048 */
    int k = idx & 255;
    int i = idx >> 8;                  /* 0..7 */
    int h = i & 3;
    int off = (i >> 2) * NHID;
    const float* wrow = Ws + ((size_t)h * NFEAT + k) * NHID;
    const float* av = a_heads + h * (2 * NHID) + off;
    float s = 0.f;
#pragma unroll 8
    for (int c = 0; c < NHID; c++) s += wrow[c] * av[c];
    g_wa[i][k] = s;
}

/* ---------------- 2c. v2s/v2d = W_out @ a_out halves ---------------------- */
__global__ void prep_v2(const float* __restrict__ W_out, const float* __restrict__ a_out) {
    int k = threadIdx.x;               /* 256 */
    const float* wrow = W_out + (size_t)k * NCLASS;
    float s = 0.f, d = 0.f;
    for (int c = 0; c < NCLASS; c++) {
        float w = wrow[c];
        s += w * a_out[c];
        d += w * a_out[NCLASS + c];
    }
    g_v2s[k] = s;
    g_v2d[k] = d;
}

/* ---------------- 3. double-buffered SGEMM: C = A[M,K] * B[K,N] ----------- */
/* BMxBN=BMx64, BK=16, 256 threads, reg tile (BM/16)x4, register-staged DB.  */
template<int BM>
__global__ void sgemm_db(const float* __restrict__ A, const float* __restrict__ B,
                         float* __restrict__ C, int N, int K, int ldc) {
    constexpr int TM = BM / 16;
    constexpr int AV = (BM * 4) / 256;          /* float4 A-loads per thread */
    __shared__ float As[16][BM];
    __shared__ float Bs[16][64];
    int tid = threadIdx.x;
    int tx = tid & 15, ty = tid >> 4;
    int row0 = blockIdx.y * BM;
    int col0 = blockIdx.x * 64;

    float acc[TM][4];
#pragma unroll
    for (int i = 0; i < TM; i++)
#pragma unroll
        for (int j = 0; j < 4; j++) acc[i][j] = 0.f;

    int ar[AV], ac[AV];
#pragma unroll
    for (int v = 0; v < AV; v++) {
        int lin = tid + v * 256;
        ar[v] = lin % BM;
        ac[v] = (lin / BM) * 4;
    }
    int br = tid >> 4;
    int bc = (tid & 15) * 4;

    float4 a_reg[AV];
    float  b_reg[4];
#pragma unroll
    for (int v = 0; v < AV; v++)
        a_reg[v] = *(const float4*)(A + (size_t)(row0 + ar[v]) * K + ac[v]);
#pragma unroll
    for (int j = 0; j < 4; j++) {
        int c = col0 + bc + j;
        b_reg[j] = (c < N) ? B[(size_t)br * N + c] : 0.f;
    }

    for (int k0 = 0; k0 < K; k0 += 16) {
#pragma unroll
        for (int v = 0; v < AV; v++) {
            As[ac[v] + 0][ar[v]] = a_reg[v].x;
            As[ac[v] + 1][ar[v]] = a_reg[v].y;
            As[ac[v] + 2][ar[v]] = a_reg[v].z;
            As[ac[v] + 3][ar[v]] = a_reg[v].w;
        }
#pragma unroll
        for (int j = 0; j < 4; j++) Bs[br][bc + j] = b_reg[j];
        __syncthreads();

        if (k0 + 16 < K) {
#pragma unroll
            for (int v = 0; v < AV; v++)
                a_reg[v] = *(const float4*)(A + (size_t)(row0 + ar[v]) * K + (k0 + 16) + ac[v]);
#pragma unroll
            for (int j = 0; j < 4; j++) {
                int c = col0 + bc + j;
                b_reg[j] = (c < N) ? B[(size_t)(k0 + 16 + br) * N + c] : 0.f;
            }
        }

#pragma unroll
        for (int kk = 0; kk < 16; kk++) {
            float ra[TM], rb[4];
#pragma unroll
            for (int i = 0; i < TM; i += 4) {
                float4 t = *(const float4*)&As[kk][ty * TM + i];
                ra[i] = t.x; ra[i + 1] = t.y; ra[i + 2] = t.z; ra[i + 3] = t.w;
            }
            float4 tb = *(const float4*)&Bs[kk][tx * 4];
            rb[0] = tb.x; rb[1] = tb.y; rb[2] = tb.z; rb[3] = tb.w;
#pragma unroll
            for (int i = 0; i < TM; i++)
#pragma unroll
                for (int j = 0; j < 4; j++)
                    acc[i][j] += ra[i] * rb[j];
        }
        __syncthreads();
    }
#pragma unroll
    for (int i = 0; i < TM; i++) {
        int r = row0 + ty * TM + i;
#pragma unroll
        for (int j = 0; j < 4; j++) {
            int c = col0 + tx * 4 + j;
            if (c < N) C[(size_t)r * ldc + c] = acc[i][j];
        }
    }
}

/* ---------------- 4. layer-1 f-scores: 8-way GEMV over x ------------------ */
__global__ void fvec1(const float* __restrict__ x) {
    int row = blockIdx.x, tid = threadIdx.x;
    float xv = x[(size_t)row * NFEAT + tid];
    float p[8];
#pragma unroll
    for (int i = 0; i < 8; i++) p[i] = xv * g_wa[i][tid];
#pragma unroll
    for (int o = 16; o > 0; o >>= 1)
#pragma unroll
        for (int i = 0; i < 8; i++) p[i] += __shfl_xor_sync(0xffffffffu, p[i], o);
    __shared__ float sp[8][8];
    int w = tid >> 5;
    if ((tid & 31) == 0)
#pragma unroll
        for (int i = 0; i < 8; i++) sp[i][w] = p[i];
    __syncthreads();
    if (tid < 8) {
        float s = 0.f;
#pragma unroll
        for (int ww = 0; ww < 8; ww++) s += sp[tid][ww];
        if (tid < 4) g_fs[tid * N_NODES + row] = s;
        else         g_fd[(tid - 4) * N_NODES + row] = s;
    }
}

/* ---------------- 5. layer-1 softmax-aggregate + ELU ---------------------- */
__global__ void agg1() {
    int row = blockIdx.x, tid = threadIdx.x;
    int h = tid >> 6, f = tid & 63;
    __shared__ int   s_col[MAXDEG];
    __shared__ float s_w[NHEADS][MAXDEG];
    __shared__ float s_rmax[8], s_rsum[8];
    __shared__ float s_m[NHEADS], s_d[NHEADS];

    int deg = g_deg[row];
    for (int k = tid; k < deg; k += 256)
        s_col[k] = g_cols[(size_t)row * MAXDEG + k];
    __syncthreads();

    float fsi = g_fs[h * N_NODES + row];
    const float* fdh = g_fd + h * N_NODES;

    float m = -1e30f;
    for (int k = f; k < deg; k += 64) {
        float e = fsi + fdh[s_col[k]];
        e = (e > 0.f) ? e : LRELU_ALPHA * e;
        s_w[h][k] = e;
        m = fmaxf(m, e);
    }
#pragma unroll
    for (int o = 16; o > 0; o >>= 1) m = fmaxf(m, __shfl_xor_sync(0xffffffffu, m, o));
    int w = tid >> 5;
    if ((tid & 31) == 0) s_rmax[w] = m;
    __syncthreads();
    if (f == 0) s_m[h] = fmaxf(s_rmax[2 * h], s_rmax[2 * h + 1]);
    __syncthreads();
    float mh = s_m[h];

    float lsum = 0.f;
    for (int k = f; k < deg; k += 64) {
        float wv = expf(s_w[h][k] - mh);
        s_w[h][k] = wv;
        lsum += wv;
    }
#pragma unroll
    for (int o = 16; o > 0; o >>= 1) lsum += __shfl_xor_sync(0xffffffffu, lsum, o);
    if ((tid & 31) == 0) s_rsum[w] = lsum;
    __syncthreads();
    if (f == 0) s_d[h] = s_rsum[2 * h] + s_rsum[2 * h + 1];
    __syncthreads();
    float inv = 1.f / s_d[h];

    float acc = 0.f;
    int base = h * NHID + f;
#pragma unroll 4
    for (int k = 0; k < deg; k++) {
        acc += s_w[h][k] * g_Wh[(size_t)s_col[k] * DHID + base];
    }
    acc *= inv;
    acc = (acc > 0.f) ? acc : expm1f(acc);       /* ELU (concat=True) */
    g_hcat[(size_t)row * DHID + tid] = acc;
}

/* ---------------- 6. layer-2 f-scores: 2-way GEMV over hcat --------------- */
__global__ void fvec2() {
    int row = blockIdx.x, tid = threadIdx.x;
    float v = g_hcat[(size_t)row * DHID + tid];
    float ps = v * g_v2s[tid];
    float pd = v * g_v2d[tid];
#pragma unroll
    for (int o = 16; o > 0; o >>= 1) {
        ps += __shfl_xor_sync(0xffffffffu, ps, o);
        pd += __shfl_xor_sync(0xffffffffu, pd, o);
    }
    __shared__ float ss[8], sd[8];
    int w = tid >> 5;
    if ((tid & 31) == 0) { ss[w] = ps; sd[w] = pd; }
    __syncthreads();
    if (tid == 0) {
        float a = 0.f, b = 0.f;
#pragma unroll
        for (int ww = 0; ww < 8; ww++) { a += ss[ww]; b += sd[ww]; }
        g_f2s[row] = a;
        g_f2d[row] = b;
    }
}

/* ---------------- 7. layer-2 softmax-aggregate (no ELU) ------------------- */
__global__ void agg2(float* __restrict__ out) {
    int row = blockIdx.x, tid = threadIdx.x;     /* 128 threads */
    __shared__ int   s_col[MAXDEG];
    __shared__ float s_w[MAXDEG];
    __shared__ float s_rmax[4], s_rsum[4];
    __shared__ float s_m, s_den;

    int deg = g_deg[row];
    for (int k = tid; k < deg; k += 128)
        s_col[k] = g_cols[(size_t)row * MAXDEG + k];
    __syncthreads();

    float fsi = g_f2s[row];
    float m = -1e30f;
    for (int k = tid; k < deg; k += 128) {
        float e = fsi + g_f2d[s_col[k]];
        e = (e > 0.f) ? e : LRELU_ALPHA * e;
        s_w[k] = e;
        m = fmaxf(m, e);
    }
#pragma unroll
    for (int o = 16; o > 0; o >>= 1) m = fmaxf(m, __shfl_xor_sync(0xffffffffu, m, o));
    int w = tid >> 5;
    if ((tid & 31) == 0) s_rmax[w] = m;
    __syncthreads();
    if (tid == 0) s_m = fmaxf(fmaxf(s_rmax[0], s_rmax[1]), fmaxf(s_rmax[2], s_rmax[3]));
    __syncthreads();
    float mh = s_m;

    float lsum = 0.f;
    for (int k = tid; k < deg; k += 128) {
        float wv = expf(s_w[k] - mh);
        s_w[k] = wv;
        lsum += wv;
    }
#pragma unroll
    for (int o = 16; o > 0; o >>= 1) lsum += __shfl_xor_sync(0xffffffffu, lsum, o);
    if ((tid & 31) == 0) s_rsum[w] = lsum;
    __syncthreads();
    if (tid == 0) s_den = s_rsum[0] + s_rsum[1] + s_rsum[2] + s_rsum[3];
    __syncthreads();
    float inv = 1.f / s_den;

    if (tid < NCLASS) {
        float acc = 0.f;
#pragma unroll 4
        for (int k = 0; k < deg; k++)
            acc += s_w[k] * g_Whc[(size_t)s_col[k] * LDC2 + tid];
        out[(size_t)row * NCLASS + tid] = acc * inv;
    }
}

/* ---------------- launch ------------------------------------------------- */
extern "C" void kernel_launch(void* const* d_in, const int* in_sizes, int n_in,
                              void* d_out, int out_size) {
    const float* x       = (const float*)d_in[0];   /* [8192,256]  */
    const float* adj     = (const float*)d_in[1];   /* [8192,8192] */
    const float* Ws      = (const float*)d_in[2];   /* [4,256,64]  */
    const float* a_heads = (const float*)d_in[3];   /* [4,128]     */
    const float* W_out   = (const float*)d_in[4];   /* [256,121]   */
    const float* a_out   = (const float*)d_in[5];   /* [242]       */
    float* out = (float*)d_out;                     /* [8192,121]  */

    float* p_Wh;   cudaGetSymbolAddress((void**)&p_Wh,   g_Wh);
    float* p_Wcat; cudaGetSymbolAddress((void**)&p_Wcat, g_Wcat);
    float* p_hcat; cudaGetSymbolAddress((void**)&p_hcat, g_hcat);
    float* p_Whc;  cudaGetSymbolAddress((void**)&p_Whc,  g_Whc);

    build_edges<<<N_NODES, 256>>>(adj);
    pack_W<<<NFEAT * DHID / 256, 256>>>(Ws);
    prep_wa<<<8, 256>>>(Ws, a_heads);
    prep_v2<<<1, 256>>>(W_out, a_out);
    {
        dim3 grid(DHID / 64, N_NODES / 128);
        sgemm_db<128><<<grid, 256>>>(x, p_Wcat, p_Wh, DHID, NFEAT, DHID);
    }
    fvec1<<<N_NODES, 256>>>(x);
    agg1<<<N_NODES, 256>>>();
    {
        dim3 grid((NCLASS + 63) / 64, N_NODES / 64);
        sgemm_db<64><<<grid, 256>>>(p_hcat, W_out, p_Whc, NCLASS, DHID, LDC2);
    }
    fvec2<<<N_NODES, 256>>>();
    agg2<<<N_NODES, 128>>>(out);
}

// round 8
// speedup vs baseline: 1.1807x; 1.1807x over previous
#include <cuda_runtime.h>
#include <math.h>

#define N_NODES 8192
#define NFEAT   256
#define NHID    64
#define NHEADS  4
#define DHID    (NHEADS*NHID)   /* 256 */
#define NCLASS  121
#define LDC2    128             /* padded ld for Whc */
#define MAXDEG  512
#define LRELU_ALPHA 0.2f

/* ---------------- scratch (static device globals; no allocs) -------------- */
__device__ float g_Wh[N_NODES * DHID];        /* 8 MB  layer-1 Wh, heads concat */
__device__ float g_Wcat[NFEAT * DHID];        /* 256 KB packed W */
__device__ float g_fs[NHEADS * N_NODES];
__device__ float g_fd[NHEADS * N_NODES];
__device__ float g_hcat[N_NODES * DHID];      /* 8 MB layer-1 output */
__device__ float g_Whc[N_NODES * LDC2];       /* 4 MB layer-2 Wh (ld=128) */
__device__ float g_v2s[DHID];
__device__ float g_v2d[DHID];
__device__ float g_f2s[N_NODES];
__device__ float g_f2d[N_NODES];
__device__ int   g_cols[(size_t)N_NODES * MAXDEG];  /* 16 MB edge lists */
__device__ int   g_deg[N_NODES];

/* ---------------- 1. build per-row edge lists (one pass over adj) --------- */
__global__ void build_edges(const float* __restrict__ adj) {
    int row = blockIdx.x;
    int tid = threadIdx.x;
    const float4* a4 = (const float4*)(adj + (size_t)row * N_NODES + tid * 32);

    float4 v[8];
    int cnt = 0;
#pragma unroll
    for (int q = 0; q < 8; q++) {
        v[q] = a4[q];
        cnt += (v[q].x > 0.f) + (v[q].y > 0.f) + (v[q].z > 0.f) + (v[q].w > 0.f);
    }

    __shared__ int s[256];
    s[tid] = cnt;
    __syncthreads();
    for (int off = 1; off < 256; off <<= 1) {
        int t = (tid >= off) ? s[tid - off] : 0;
        __syncthreads();
        s[tid] += t;
        __syncthreads();
    }
    int pos = s[tid] - cnt;            /* exclusive prefix */
    if (tid == 0) {
        int total = s[255];
        g_deg[row] = total < MAXDEG ? total : MAXDEG;
    }

    int* outc = g_cols + (size_t)row * MAXDEG;
#pragma unroll
    for (int q = 0; q < 8; q++) {
        int base = tid * 32 + q * 4;
        if (v[q].x > 0.f) { if (pos < MAXDEG) outc[pos] = base + 0; pos++; }
        if (v[q].y > 0.f) { if (pos < MAXDEG) outc[pos] = base + 1; pos++; }
        if (v[q].z > 0.f) { if (pos < MAXDEG) outc[pos] = base + 2; pos++; }
        if (v[q].w > 0.f) { if (pos < MAXDEG) outc[pos] = base + 3; pos++; }
    }
}

/* ---------------- 2. pack Ws [H,256,64] -> Wcat [256,256] ----------------- */
__global__ void pack_W(const float* __restrict__ Ws) {
    int idx = blockIdx.x * blockDim.x + threadIdx.x;
    int n = idx & 255;
    int k = idx >> 8;
    int h = n >> 6, c = n & 63;
    g_Wcat[k * DHID + n] = Ws[((size_t)h * NFEAT + k) * NHID + c];
}

/* ---------------- 2b. v2 = W_out @ a_out halves (warp per row) ------------ */
__global__ void prep_v2(const float* __restrict__ W_out, const float* __restrict__ a_out) {
    int warp = (blockIdx.x << 3) + (threadIdx.x >> 5);   /* 32 blocks * 8 warps = 256 */
    int lane = threadIdx.x & 31;
    const float* wrow = W_out + (size_t)warp * NCLASS;
    float s = 0.f, d = 0.f;
    for (int c = lane; c < NCLASS; c += 32) {
        float w = wrow[c];
        s += w * a_out[c];
        d += w * a_out[NCLASS + c];
    }
#pragma unroll
    for (int o = 16; o > 0; o >>= 1) {
        s += __shfl_xor_sync(0xffffffffu, s, o);
        d += __shfl_xor_sync(0xffffffffu, d, o);
    }
    if (lane == 0) { g_v2s[warp] = s; g_v2d[warp] = d; }
}

/* ---------------- 3. SGEMM1: Wh = x @ Wcat, fused f_src/f_dst ------------- */
/* BM=128, BN=64 (= one head), BK=16, 256 thr, 8x4 reg tile, reg-staged DB.  */
__global__ void sgemm1(const float* __restrict__ A, const float* __restrict__ a_heads) {
    __shared__ float As[16][128];
    __shared__ float Bs[16][64];
    __shared__ float s_as[64], s_ad[64];
    int tid = threadIdx.x;
    int tx = tid & 15, ty = tid >> 4;
    int h = blockIdx.x;                 /* head = column tile */
    int row0 = blockIdx.y * 128;
    int col0 = h * 64;
    const int K = NFEAT;

    if (tid < 64)       s_as[tid]      = a_heads[h * 128 + tid];
    else if (tid < 128) s_ad[tid - 64] = a_heads[h * 128 + tid]; /* 64..127 = dst half */

    float acc[8][4];
#pragma unroll
    for (int i = 0; i < 8; i++)
#pragma unroll
        for (int j = 0; j < 4; j++) acc[i][j] = 0.f;

    int ar0 = tid & 127,          ac0 = (tid >> 7) * 4;       /* lin = tid       */
    int ar1 = tid & 127,          ac1 = ((tid + 256) >> 7) * 4; /* lin = tid+256 */
    int br = tid >> 4;
    int bc = (tid & 15) * 4;

    float4 a_reg0 = *(const float4*)(A + (size_t)(row0 + ar0) * K + ac0);
    float4 a_reg1 = *(const float4*)(A + (size_t)(row0 + ar1) * K + ac1);
    float4 b_reg  = *(const float4*)(g_Wcat + (size_t)br * DHID + col0 + bc);
    __syncthreads();   /* covers s_as/s_ad */

    for (int k0 = 0; k0 < K; k0 += 16) {
        As[ac0 + 0][ar0] = a_reg0.x; As[ac0 + 1][ar0] = a_reg0.y;
        As[ac0 + 2][ar0] = a_reg0.z; As[ac0 + 3][ar0] = a_reg0.w;
        As[ac1 + 0][ar1] = a_reg1.x; As[ac1 + 1][ar1] = a_reg1.y;
        As[ac1 + 2][ar1] = a_reg1.z; As[ac1 + 3][ar1] = a_reg1.w;
        *(float4*)&Bs[br][bc] = b_reg;
        __syncthreads();

        if (k0 + 16 < K) {
            a_reg0 = *(const float4*)(A + (size_t)(row0 + ar0) * K + (k0 + 16) + ac0);
            a_reg1 = *(const float4*)(A + (size_t)(row0 + ar1) * K + (k0 + 16) + ac1);
            b_reg  = *(const float4*)(g_Wcat + (size_t)(k0 + 16 + br) * DHID + col0 + bc);
        }

#pragma unroll
        for (int kk = 0; kk < 16; kk++) {
            float4 ra0 = *(const float4*)&As[kk][ty * 8];
            float4 ra1 = *(const float4*)&As[kk][ty * 8 + 4];
            float4 rb  = *(const float4*)&Bs[kk][tx * 4];
            float ra[8] = {ra0.x, ra0.y, ra0.z, ra0.w, ra1.x, ra1.y, ra1.z, ra1.w};
#pragma unroll
            for (int i = 0; i < 8; i++) {
                acc[i][0] += ra[i] * rb.x;
                acc[i][1] += ra[i] * rb.y;
                acc[i][2] += ra[i] * rb.z;
                acc[i][3] += ra[i] * rb.w;
            }
        }
        __syncthreads();
    }

    /* store C + fused per-head f-scores (reduce across tx = 16 lanes) */
#pragma unroll
    for (int i = 0; i < 8; i++) {
        int r = row0 + ty * 8 + i;
        *(float4*)(g_Wh + (size_t)r * DHID + col0 + tx * 4) =
            make_float4(acc[i][0], acc[i][1], acc[i][2], acc[i][3]);
        float ps = 0.f, pd = 0.f;
#pragma unroll
        for (int j = 0; j < 4; j++) {
            int c = tx * 4 + j;
            ps += acc[i][j] * s_as[c];
            pd += acc[i][j] * s_ad[c];
        }
#pragma unroll
        for (int o = 8; o > 0; o >>= 1) {
            ps += __shfl_xor_sync(0xffffffffu, ps, o);
            pd += __shfl_xor_sync(0xffffffffu, pd, o);
        }
        if (tx == 0) {
            g_fs[h * N_NODES + r] = ps;
            g_fd[h * N_NODES + r] = pd;
        }
    }
}

/* ---------------- 3b. SGEMM2: Whc = hcat @ W_out (N=121, ldc=128) --------- */
__global__ void sgemm2(const float* __restrict__ A, const float* __restrict__ B) {
    __shared__ float As[16][128];
    __shared__ float Bs[16][64];
    int tid = threadIdx.x;
    int tx = tid & 15, ty = tid >> 4;
    int row0 = blockIdx.y * 128;
    int col0 = blockIdx.x * 64;
    const int K = DHID, N = NCLASS;

    float acc[8][4];
#pragma unroll
    for (int i = 0; i < 8; i++)
#pragma unroll
        for (int j = 0; j < 4; j++) acc[i][j] = 0.f;

    int ar0 = tid & 127,          ac0 = (tid >> 7) * 4;
    int ar1 = tid & 127,          ac1 = ((tid + 256) >> 7) * 4;
    int br = tid >> 4;
    int bc = (tid & 15) * 4;

    float4 a_reg0 = *(const float4*)(A + (size_t)(row0 + ar0) * K + ac0);
    float4 a_reg1 = *(const float4*)(A + (size_t)(row0 + ar1) * K + ac1);
    float  b_reg[4];
#pragma unroll
    for (int j = 0; j < 4; j++) {
        int c = col0 + bc + j;
        b_reg[j] = (c < N) ? B[(size_t)br * N + c] : 0.f;
    }

    for (int k0 = 0; k0 < K; k0 += 16) {
        As[ac0 + 0][ar0] = a_reg0.x; As[ac0 + 1][ar0] = a_reg0.y;
        As[ac0 + 2][ar0] = a_reg0.z; As[ac0 + 3][ar0] = a_reg0.w;
        As[ac1 + 0][ar1] = a_reg1.x; As[ac1 + 1][ar1] = a_reg1.y;
        As[ac1 + 2][ar1] = a_reg1.z; As[ac1 + 3][ar1] = a_reg1.w;
#pragma unroll
        for (int j = 0; j < 4; j++) Bs[br][bc + j] = b_reg[j];
        __syncthreads();

        if (k0 + 16 < K) {
            a_reg0 = *(const float4*)(A + (size_t)(row0 + ar0) * K + (k0 + 16) + ac0);
            a_reg1 = *(const float4*)(A + (size_t)(row0 + ar1) * K + (k0 + 16) + ac1);
#pragma unroll
            for (int j = 0; j < 4; j++) {
                int c = col0 + bc + j;
                b_reg[j] = (c < N) ? B[(size_t)(k0 + 16 + br) * N + c] : 0.f;
            }
        }

#pragma unroll
        for (int kk = 0; kk < 16; kk++) {
            float4 ra0 = *(const float4*)&As[kk][ty * 8];
            float4 ra1 = *(const float4*)&As[kk][ty * 8 + 4];
            float4 rb  = *(const float4*)&Bs[kk][tx * 4];
            float ra[8] = {ra0.x, ra0.y, ra0.z, ra0.w, ra1.x, ra1.y, ra1.z, ra1.w};
#pragma unroll
            for (int i = 0; i < 8; i++) {
                acc[i][0] += ra[i] * rb.x;
                acc[i][1] += ra[i] * rb.y;
                acc[i][2] += ra[i] * rb.z;
                acc[i][3] += ra[i] * rb.w;
            }
        }
        __syncthreads();
    }
#pragma unroll
    for (int i = 0; i < 8; i++) {
        int r = row0 + ty * 8 + i;
#pragma unroll
        for (int j = 0; j < 4; j++) {
            int c = col0 + tx * 4 + j;
            if (c < N) g_Whc[(size_t)r * LDC2 + c] = acc[i][j];
        }
    }
}

/* ---------------- 5. layer-1 softmax-aggregate + ELU + fused f2 ----------- */
__global__ void agg1() {
    int row = blockIdx.x, tid = threadIdx.x;
    int h = tid >> 6, f = tid & 63;
    __shared__ int   s_col[MAXDEG];
    __shared__ float s_w[NHEADS][MAXDEG];
    __shared__ float s_rmax[8], s_rsum[8];
    __shared__ float s_m[NHEADS], s_d[NHEADS];
    __shared__ float s_ps[8], s_pd[8];

    int deg = g_deg[row];
    for (int k = tid; k < deg; k += 256)
        s_col[k] = g_cols[(size_t)row * MAXDEG + k];
    __syncthreads();

    float fsi = g_fs[h * N_NODES + row];
    const float* fdh = g_fd + h * N_NODES;

    float m = -1e30f;
    for (int k = f; k < deg; k += 64) {
        float e = fsi + fdh[s_col[k]];
        e = (e > 0.f) ? e : LRELU_ALPHA * e;
        s_w[h][k] = e;
        m = fmaxf(m, e);
    }
#pragma unroll
    for (int o = 16; o > 0; o >>= 1) m = fmaxf(m, __shfl_xor_sync(0xffffffffu, m, o));
    int w = tid >> 5;
    if ((tid & 31) == 0) s_rmax[w] = m;
    __syncthreads();
    if (f == 0) s_m[h] = fmaxf(s_rmax[2 * h], s_rmax[2 * h + 1]);
    __syncthreads();
    float mh = s_m[h];

    float lsum = 0.f;
    for (int k = f; k < deg; k += 64) {
        float wv = expf(s_w[h][k] - mh);
        s_w[h][k] = wv;
        lsum += wv;
    }
#pragma unroll
    for (int o = 16; o > 0; o >>= 1) lsum += __shfl_xor_sync(0xffffffffu, lsum, o);
    if ((tid & 31) == 0) s_rsum[w] = lsum;
    __syncthreads();
    if (f == 0) s_d[h] = s_rsum[2 * h] + s_rsum[2 * h + 1];
    __syncthreads();
    float inv = 1.f / s_d[h];

    float acc = 0.f;
    int base = h * NHID + f;
#pragma unroll 4
    for (int k = 0; k < deg; k++) {
        acc += s_w[h][k] * g_Wh[(size_t)s_col[k] * DHID + base];
    }
    acc *= inv;
    acc = (acc > 0.f) ? acc : expm1f(acc);       /* ELU (concat=True) */
    g_hcat[(size_t)row * DHID + tid] = acc;

    /* fused layer-2 f-scores: f2 = hcat_row . v2 */
    float ps = acc * g_v2s[tid];
    float pd = acc * g_v2d[tid];
#pragma unroll
    for (int o = 16; o > 0; o >>= 1) {
        ps += __shfl_xor_sync(0xffffffffu, ps, o);
        pd += __shfl_xor_sync(0xffffffffu, pd, o);
    }
    if ((tid & 31) == 0) { s_ps[w] = ps; s_pd[w] = pd; }
    __syncthreads();
    if (tid == 0) {
        float a = 0.f, b = 0.f;
#pragma unroll
        for (int ww = 0; ww < 8; ww++) { a += s_ps[ww]; b += s_pd[ww]; }
        g_f2s[row] = a;
        g_f2d[row] = b;
    }
}

/* ---------------- 7. layer-2 softmax-aggregate (no ELU) ------------------- */
__global__ void agg2(float* __restrict__ out) {
    int row = blockIdx.x, tid = threadIdx.x;     /* 128 threads */
    __shared__ int   s_col[MAXDEG];
    __shared__ float s_w[MAXDEG];
    __shared__ float s_rmax[4], s_rsum[4];
    __shared__ float s_m, s_den;

    int deg = g_deg[row];
    for (int k = tid; k < deg; k += 128)
        s_col[k] = g_cols[(size_t)row * MAXDEG + k];
    __syncthreads();

    float fsi = g_f2s[row];
    float m = -1e30f;
    for (int k = tid; k < deg; k += 128) {
        float e = fsi + g_f2d[s_col[k]];
        e = (e > 0.f) ? e : LRELU_ALPHA * e;
        s_w[k] = e;
        m = fmaxf(m, e);
    }
#pragma unroll
    for (int o = 16; o > 0; o >>= 1) m = fmaxf(m, __shfl_xor_sync(0xffffffffu, m, o));
    int w = tid >> 5;
    if ((tid & 31) == 0) s_rmax[w] = m;
    __syncthreads();
    if (tid == 0) s_m = fmaxf(fmaxf(s_rmax[0], s_rmax[1]), fmaxf(s_rmax[2], s_rmax[3]));
    __syncthreads();
    float mh = s_m;

    float lsum = 0.f;
    for (int k = tid; k < deg; k += 128) {
        float wv = expf(s_w[k] - mh);
        s_w[k] = wv;
        lsum += wv;
    }
#pragma unroll
    for (int o = 16; o > 0; o >>= 1) lsum += __shfl_xor_sync(0xffffffffu, lsum, o);
    if ((tid & 31) == 0) s_rsum[w] = lsum;
    __syncthreads();
    if (tid == 0) s_den = s_rsum[0] + s_rsum[1] + s_rsum[2] + s_rsum[3];
    __syncthreads();
    float inv = 1.f / s_den;

    if (tid < NCLASS) {
        float acc = 0.f;
#pragma unroll 4
        for (int k = 0; k < deg; k++)
            acc += s_w[k] * g_Whc[(size_t)s_col[k] * LDC2 + tid];
        out[(size_t)row * NCLASS + tid] = acc * inv;
    }
}

/* ---------------- launch ------------------------------------------------- */
extern "C" void kernel_launch(void* const* d_in, const int* in_sizes, int n_in,
                              void* d_out, int out_size) {
    const float* x       = (const float*)d_in[0];   /* [8192,256]  */
    const float* adj     = (const float*)d_in[1];   /* [8192,8192] */
    const float* Ws      = (const float*)d_in[2];   /* [4,256,64]  */
    const float* a_heads = (const float*)d_in[3];   /* [4,128]     */
    const float* W_out   = (const float*)d_in[4];   /* [256,121]   */
    const float* a_out   = (const float*)d_in[5];   /* [242]       */
    float* out = (float*)d_out;                     /* [8192,121]  */

    float* p_hcat; cudaGetSymbolAddress((void**)&p_hcat, g_hcat);

    pack_W<<<NFEAT * DHID / 256, 256>>>(Ws);
    prep_v2<<<32, 256>>>(W_out, a_out);
    build_edges<<<N_NODES, 256>>>(adj);
    {
        dim3 grid(NHEADS, N_NODES / 128);
        sgemm1<<<grid, 256>>>(x, a_heads);
    }
    agg1<<<N_NODES, 256>>>();
    {
        dim3 grid((NCLASS + 63) / 64, N_NODES / 128);
        sgemm2<<<grid, 256>>>(p_hcat, W_out);
    }
    agg2<<<N_NODES, 128>>>(out);
}

// round 9
// speedup vs baseline: 1.3438x; 1.1381x over previous
#include <cuda_runtime.h>
#include <cuda_fp16.h>
#include <math.h>

#define N_NODES 8192
#define NFEAT   256
#define NHID    64
#define NHEADS  4
#define DHID    (NHEADS*NHID)   /* 256 */
#define NCLASS  121
#define LDC2    128             /* padded ld for Whc (halfs) */
#define MAXDEG  512
#define LRELU_ALPHA 0.2f

/* ---------------- scratch (static device globals; no allocs) -------------- */
__device__ __half g_Wh_h[N_NODES * DHID];     /* 4 MB layer-1 Wh (fp16, gather-only) */
__device__ float  g_Wcat[NFEAT * DHID];       /* 256 KB packed W */
__device__ float  g_fs[NHEADS * N_NODES];
__device__ float  g_fd[NHEADS * N_NODES];
__device__ float  g_hcat[N_NODES * DHID];     /* 8 MB layer-1 output (fp32, GEMM2 A) */
__device__ __half g_Whc_h[N_NODES * LDC2];    /* 2 MB layer-2 Wh (fp16, gather-only) */
__device__ float  g_v2s[DHID];
__device__ float  g_v2d[DHID];
__device__ float  g_f2s[N_NODES];
__device__ float  g_f2d[N_NODES];
__device__ int    g_cols[(size_t)N_NODES * MAXDEG];  /* 16 MB edge lists */
__device__ int    g_deg[N_NODES];

/* ---------------- 1. build per-row edge lists (one pass over adj) --------- */
__global__ void build_edges(const float* __restrict__ adj) {
    int row = blockIdx.x;
    int tid = threadIdx.x;
    const float4* a4 = (const float4*)(adj + (size_t)row * N_NODES + tid * 32);

    float4 v[8];
    int cnt = 0;
#pragma unroll
    for (int q = 0; q < 8; q++) {
        v[q] = a4[q];
        cnt += (v[q].x > 0.f) + (v[q].y > 0.f) + (v[q].z > 0.f) + (v[q].w > 0.f);
    }

    __shared__ int s[256];
    s[tid] = cnt;
    __syncthreads();
    for (int off = 1; off < 256; off <<= 1) {
        int t = (tid >= off) ? s[tid - off] : 0;
        __syncthreads();
        s[tid] += t;
        __syncthreads();
    }
    int pos = s[tid] - cnt;            /* exclusive prefix */
    if (tid == 0) {
        int total = s[255];
        g_deg[row] = total < MAXDEG ? total : MAXDEG;
    }

    int* outc = g_cols + (size_t)row * MAXDEG;
#pragma unroll
    for (int q = 0; q < 8; q++) {
        int base = tid * 32 + q * 4;
        if (v[q].x > 0.f) { if (pos < MAXDEG) outc[pos] = base + 0; pos++; }
        if (v[q].y > 0.f) { if (pos < MAXDEG) outc[pos] = base + 1; pos++; }
        if (v[q].z > 0.f) { if (pos < MAXDEG) outc[pos] = base + 2; pos++; }
        if (v[q].w > 0.f) { if (pos < MAXDEG) outc[pos] = base + 3; pos++; }
    }
}

/* ---------------- 2. pack Ws [H,256,64] -> Wcat [256,256] ----------------- */
__global__ void pack_W(const float* __restrict__ Ws) {
    int idx = blockIdx.x * blockDim.x + threadIdx.x;
    int n = idx & 255;
    int k = idx >> 8;
    int h = n >> 6, c = n & 63;
    g_Wcat[k * DHID + n] = Ws[((size_t)h * NFEAT + k) * NHID + c];
}

/* ---------------- 2b. v2 = W_out @ a_out halves (warp per row) ------------ */
__global__ void prep_v2(const float* __restrict__ W_out, const float* __restrict__ a_out) {
    int warp = (blockIdx.x << 3) + (threadIdx.x >> 5);   /* 32 blocks * 8 warps = 256 */
    int lane = threadIdx.x & 31;
    const float* wrow = W_out + (size_t)warp * NCLASS;
    float s = 0.f, d = 0.f;
    for (int c = lane; c < NCLASS; c += 32) {
        float w = wrow[c];
        s += w * a_out[c];
        d += w * a_out[NCLASS + c];
    }
#pragma unroll
    for (int o = 16; o > 0; o >>= 1) {
        s += __shfl_xor_sync(0xffffffffu, s, o);
        d += __shfl_xor_sync(0xffffffffu, d, o);
    }
    if (lane == 0) { g_v2s[warp] = s; g_v2d[warp] = d; }
}

/* ---------------- 3. SGEMM1: Wh = x @ Wcat, fused f_src/f_dst, fp16 out --- */
__global__ void sgemm1(const float* __restrict__ A, const float* __restrict__ a_heads) {
    __shared__ float As[16][128];
    __shared__ float Bs[16][64];
    __shared__ float s_as[64], s_ad[64];
    int tid = threadIdx.x;
    int tx = tid & 15, ty = tid >> 4;
    int h = blockIdx.x;                 /* head = column tile */
    int row0 = blockIdx.y * 128;
    int col0 = h * 64;
    const int K = NFEAT;

    if (tid < 64)       s_as[tid]      = a_heads[h * 128 + tid];
    else if (tid < 128) s_ad[tid - 64] = a_heads[h * 128 + tid];

    float acc[8][4];
#pragma unroll
    for (int i = 0; i < 8; i++)
#pragma unroll
        for (int j = 0; j < 4; j++) acc[i][j] = 0.f;

    int ar0 = tid & 127,          ac0 = (tid >> 7) * 4;
    int ar1 = tid & 127,          ac1 = ((tid + 256) >> 7) * 4;
    int br = tid >> 4;
    int bc = (tid & 15) * 4;

    float4 a_reg0 = *(const float4*)(A + (size_t)(row0 + ar0) * K + ac0);
    float4 a_reg1 = *(const float4*)(A + (size_t)(row0 + ar1) * K + ac1);
    float4 b_reg  = *(const float4*)(g_Wcat + (size_t)br * DHID + col0 + bc);
    __syncthreads();   /* covers s_as/s_ad */

    for (int k0 = 0; k0 < K; k0 += 16) {
        As[ac0 + 0][ar0] = a_reg0.x; As[ac0 + 1][ar0] = a_reg0.y;
        As[ac0 + 2][ar0] = a_reg0.z; As[ac0 + 3][ar0] = a_reg0.w;
        As[ac1 + 0][ar1] = a_reg1.x; As[ac1 + 1][ar1] = a_reg1.y;
        As[ac1 + 2][ar1] = a_reg1.z; As[ac1 + 3][ar1] = a_reg1.w;
        *(float4*)&Bs[br][bc] = b_reg;
        __syncthreads();

        if (k0 + 16 < K) {
            a_reg0 = *(const float4*)(A + (size_t)(row0 + ar0) * K + (k0 + 16) + ac0);
            a_reg1 = *(const float4*)(A + (size_t)(row0 + ar1) * K + (k0 + 16) + ac1);
            b_reg  = *(const float4*)(g_Wcat + (size_t)(k0 + 16 + br) * DHID + col0 + bc);
        }

#pragma unroll
        for (int kk = 0; kk < 16; kk++) {
            float4 ra0 = *(const float4*)&As[kk][ty * 8];
            float4 ra1 = *(const float4*)&As[kk][ty * 8 + 4];
            float4 rb  = *(const float4*)&Bs[kk][tx * 4];
            float ra[8] = {ra0.x, ra0.y, ra0.z, ra0.w, ra1.x, ra1.y, ra1.z, ra1.w};
#pragma unroll
            for (int i = 0; i < 8; i++) {
                acc[i][0] += ra[i] * rb.x;
                acc[i][1] += ra[i] * rb.y;
                acc[i][2] += ra[i] * rb.z;
                acc[i][3] += ra[i] * rb.w;
            }
        }
        __syncthreads();
    }

    /* store C (fp16) + fused per-head f-scores (fp32 accs) */
#pragma unroll
    for (int i = 0; i < 8; i++) {
        int r = row0 + ty * 8 + i;
        __half2* dst = (__half2*)(g_Wh_h + (size_t)r * DHID + col0 + tx * 4);
        dst[0] = __floats2half2_rn(acc[i][0], acc[i][1]);
        dst[1] = __floats2half2_rn(acc[i][2], acc[i][3]);
        float ps = 0.f, pd = 0.f;
#pragma unroll
        for (int j = 0; j < 4; j++) {
            int c = tx * 4 + j;
            ps += acc[i][j] * s_as[c];
            pd += acc[i][j] * s_ad[c];
        }
#pragma unroll
        for (int o = 8; o > 0; o >>= 1) {
            ps += __shfl_xor_sync(0xffffffffu, ps, o);
            pd += __shfl_xor_sync(0xffffffffu, pd, o);
        }
        if (tx == 0) {
            g_fs[h * N_NODES + r] = ps;
            g_fd[h * N_NODES + r] = pd;
        }
    }
}

/* ---------------- 3b. SGEMM2: Whc = hcat @ W_out -> fp16 (ld 128) --------- */
__global__ void sgemm2(const float* __restrict__ A, const float* __restrict__ B) {
    __shared__ float As[16][128];
    __shared__ float Bs[16][64];
    int tid = threadIdx.x;
    int tx = tid & 15, ty = tid >> 4;
    int row0 = blockIdx.y * 128;
    int col0 = blockIdx.x * 64;
    const int K = DHID, N = NCLASS;

    float acc[8][4];
#pragma unroll
    for (int i = 0; i < 8; i++)
#pragma unroll
        for (int j = 0; j < 4; j++) acc[i][j] = 0.f;

    int ar0 = tid & 127,          ac0 = (tid >> 7) * 4;
    int ar1 = tid & 127,          ac1 = ((tid + 256) >> 7) * 4;
    int br = tid >> 4;
    int bc = (tid & 15) * 4;

    float4 a_reg0 = *(const float4*)(A + (size_t)(row0 + ar0) * K + ac0);
    float4 a_reg1 = *(const float4*)(A + (size_t)(row0 + ar1) * K + ac1);
    float  b_reg[4];
#pragma unroll
    for (int j = 0; j < 4; j++) {
        int c = col0 + bc + j;
        b_reg[j] = (c < N) ? B[(size_t)br * N + c] : 0.f;
    }

    for (int k0 = 0; k0 < K; k0 += 16) {
        As[ac0 + 0][ar0] = a_reg0.x; As[ac0 + 1][ar0] = a_reg0.y;
        As[ac0 + 2][ar0] = a_reg0.z; As[ac0 + 3][ar0] = a_reg0.w;
        As[ac1 + 0][ar1] = a_reg1.x; As[ac1 + 1][ar1] = a_reg1.y;
        As[ac1 + 2][ar1] = a_reg1.z; As[ac1 + 3][ar1] = a_reg1.w;
#pragma unroll
        for (int j = 0; j < 4; j++) Bs[br][bc + j] = b_reg[j];
        __syncthreads();

        if (k0 + 16 < K) {
            a_reg0 = *(const float4*)(A + (size_t)(row0 + ar0) * K + (k0 + 16) + ac0);
            a_reg1 = *(const float4*)(A + (size_t)(row0 + ar1) * K + (k0 + 16) + ac1);
#pragma unroll
            for (int j = 0; j < 4; j++) {
                int c = col0 + bc + j;
                b_reg[j] = (c < N) ? B[(size_t)(k0 + 16 + br) * N + c] : 0.f;
            }
        }

#pragma unroll
        for (int kk = 0; kk < 16; kk++) {
            float4 ra0 = *(const float4*)&As[kk][ty * 8];
            float4 ra1 = *(const float4*)&As[kk][ty * 8 + 4];
            float4 rb  = *(const float4*)&Bs[kk][tx * 4];
            float ra[8] = {ra0.x, ra0.y, ra0.z, ra0.w, ra1.x, ra1.y, ra1.z, ra1.w};
#pragma unroll
            for (int i = 0; i < 8; i++) {
                acc[i][0] += ra[i] * rb.x;
                acc[i][1] += ra[i] * rb.y;
                acc[i][2] += ra[i] * rb.z;
                acc[i][3] += ra[i] * rb.w;
            }
        }
        __syncthreads();
    }
#pragma unroll
    for (int i = 0; i < 8; i++) {
        int r = row0 + ty * 8 + i;
#pragma unroll
        for (int j = 0; j < 4; j++) {
            int c = col0 + tx * 4 + j;
            if (c < LDC2)
                g_Whc_h[(size_t)r * LDC2 + c] = __float2half_rn(c < N ? acc[i][j] : 0.f);
        }
    }
}

/* ---------------- 5. layer-1 softmax-aggregate + ELU + fused f2 ----------- */
/* 256 threads. Softmax: 4 heads x 64 lanes. Gather: 2 edge-chunks x 128     */
/* half2 lanes (512B per edge-row instead of 1KB).                            */
__global__ void agg1() {
    int row = blockIdx.x, tid = threadIdx.x;
    int h = tid >> 6, f = tid & 63;
    __shared__ int    s_col[MAXDEG];
    __shared__ float  s_w[NHEADS][MAXDEG];
    __shared__ float  s_rmax[8], s_rsum[8];
    __shared__ float  s_m[NHEADS], s_d[NHEADS];
    __shared__ float2 s_acc[128];
    __shared__ float  s_ps[4], s_pd[4];

    int deg = g_deg[row];
    for (int k = tid; k < deg; k += 256)
        s_col[k] = g_cols[(size_t)row * MAXDEG + k];
    __syncthreads();

    float fsi = g_fs[h * N_NODES + row];
    const float* fdh = g_fd + h * N_NODES;

    float m = -1e30f;
    for (int k = f; k < deg; k += 64) {
        float e = fsi + fdh[s_col[k]];
        e = (e > 0.f) ? e : LRELU_ALPHA * e;
        s_w[h][k] = e;
        m = fmaxf(m, e);
    }
#pragma unroll
    for (int o = 16; o > 0; o >>= 1) m = fmaxf(m, __shfl_xor_sync(0xffffffffu, m, o));
    int w = tid >> 5;
    if ((tid & 31) == 0) s_rmax[w] = m;
    __syncthreads();
    if (f == 0) s_m[h] = fmaxf(s_rmax[2 * h], s_rmax[2 * h + 1]);
    __syncthreads();
    float mh = s_m[h];

    float lsum = 0.f;
    for (int k = f; k < deg; k += 64) {
        float wv = expf(s_w[h][k] - mh);
        s_w[h][k] = wv;
        lsum += wv;
    }
#pragma unroll
    for (int o = 16; o > 0; o >>= 1) lsum += __shfl_xor_sync(0xffffffffu, lsum, o);
    if ((tid & 31) == 0) s_rsum[w] = lsum;
    __syncthreads();
    if (f == 0) s_d[h] = s_rsum[2 * h] + s_rsum[2 * h + 1];
    __syncthreads();

    /* gather: thread (chunk, ttid) handles features 2*ttid,2*ttid+1, edges k=chunk,chunk+2,... */
    int ttid = tid & 127;
    int chunk = tid >> 7;
    int feat2 = ttid * 2;
    int hh = feat2 >> 6;
    const float* wrow = s_w[hh];
    float ax = 0.f, ay = 0.f;
    for (int k = chunk; k < deg; k += 2) {
        float wv = wrow[k];
        float2 fv = __half22float2(*(const __half2*)(g_Wh_h + (size_t)s_col[k] * DHID + feat2));
        ax += wv * fv.x;
        ay += wv * fv.y;
    }
    if (chunk == 1) s_acc[ttid] = make_float2(ax, ay);
    __syncthreads();
    float ps = 0.f, pd = 0.f;
    if (chunk == 0) {
        ax += s_acc[ttid].x;
        ay += s_acc[ttid].y;
        float inv = 1.f / s_d[hh];
        ax *= inv; ay *= inv;
        ax = (ax > 0.f) ? ax : expm1f(ax);
        ay = (ay > 0.f) ? ay : expm1f(ay);
        *(float2*)(g_hcat + (size_t)row * DHID + feat2) = make_float2(ax, ay);
        ps = ax * g_v2s[feat2] + ay * g_v2s[feat2 + 1];
        pd = ax * g_v2d[feat2] + ay * g_v2d[feat2 + 1];
#pragma unroll
        for (int o = 16; o > 0; o >>= 1) {
            ps += __shfl_xor_sync(0xffffffffu, ps, o);
            pd += __shfl_xor_sync(0xffffffffu, pd, o);
        }
        if ((tid & 31) == 0) { s_ps[tid >> 5] = ps; s_pd[tid >> 5] = pd; }
    }
    __syncthreads();
    if (tid == 0) {
        g_f2s[row] = s_ps[0] + s_ps[1] + s_ps[2] + s_ps[3];
        g_f2d[row] = s_pd[0] + s_pd[1] + s_pd[2] + s_pd[3];
    }
}

/* ---------------- 7. layer-2 softmax-aggregate (no ELU) ------------------- */
/* 128 threads. Gather: 2 edge-chunks x 64 half2 lanes (256B per edge-row).  */
__global__ void agg2(float* __restrict__ out) {
    int row = blockIdx.x, tid = threadIdx.x;
    __shared__ int    s_col[MAXDEG];
    __shared__ float  s_w[MAXDEG];
    __shared__ float  s_rmax[4], s_rsum[4];
    __shared__ float  s_m, s_den;
    __shared__ float2 s_acc[64];

    int deg = g_deg[row];
    for (int k = tid; k < deg; k += 128)
        s_col[k] = g_cols[(size_t)row * MAXDEG + k];
    __syncthreads();

    float fsi = g_f2s[row];
    float m = -1e30f;
    for (int k = tid; k < deg; k += 128) {
        float e = fsi + g_f2d[s_col[k]];
        e = (e > 0.f) ? e : LRELU_ALPHA * e;
        s_w[k] = e;
        m = fmaxf(m, e);
    }
#pragma unroll
    for (int o = 16; o > 0; o >>= 1) m = fmaxf(m, __shfl_xor_sync(0xffffffffu, m, o));
    int w = tid >> 5;
    if ((tid & 31) == 0) s_rmax[w] = m;
    __syncthreads();
    if (tid == 0) s_m = fmaxf(fmaxf(s_rmax[0], s_rmax[1]), fmaxf(s_rmax[2], s_rmax[3]));
    __syncthreads();
    float mh = s_m;

    float lsum = 0.f;
    for (int k = tid; k < deg; k += 128) {
        float wv = expf(s_w[k] - mh);
        s_w[k] = wv;
        lsum += wv;
    }
#pragma unroll
    for (int o = 16; o > 0; o >>= 1) lsum += __shfl_xor_sync(0xffffffffu, lsum, o);
    if ((tid & 31) == 0) s_rsum[w] = lsum;
    __syncthreads();
    if (tid == 0) s_den = s_rsum[0] + s_rsum[1] + s_rsum[2] + s_rsum[3];
    __syncthreads();
    float inv = 1.f / s_den;

    int ttid = tid & 63;
    int chunk = tid >> 6;
    int feat2 = ttid * 2;
    float ax = 0.f, ay = 0.f;
    for (int k = chunk; k < deg; k += 2) {
        float wv = s_w[k];
        float2 fv = __half22float2(*(const __half2*)(g_Whc_h + (size_t)s_col[k] * LDC2 + feat2));
        ax += wv * fv.x;
        ay += wv * fv.y;
    }
    if (chunk == 1) s_acc[ttid] = make_float2(ax, ay);
    __syncthreads();
    if (chunk == 0) {
        ax = (ax + s_acc[ttid].x) * inv;
        ay = (ay + s_acc[ttid].y) * inv;
        if (feat2     < NCLASS) out[(size_t)row * NCLASS + feat2]     = ax;
        if (feat2 + 1 < NCLASS) out[(size_t)row * NCLASS + feat2 + 1] = ay;
    }
}

/* ---------------- launch ------------------------------------------------- */
extern "C" void kernel_launch(void* const* d_in, const int* in_sizes, int n_in,
                              void* d_out, int out_size) {
    const float* x       = (const float*)d_in[0];   /* [8192,256]  */
    const float* adj     = (const float*)d_in[1];   /* [8192,8192] */
    const float* Ws      = (const float*)d_in[2];   /* [4,256,64]  */
    const float* a_heads = (const float*)d_in[3];   /* [4,128]     */
    const float* W_out   = (const float*)d_in[4];   /* [256,121]   */
    const float* a_out   = (const float*)d_in[5];   /* [242]       */
    float* out = (float*)d_out;                     /* [8192,121]  */

    /* side stream + events created once (host resources only; the launched
       work is identical on every call, incl. the captured graph) */
    static cudaStream_t s_side = 0;
    static cudaEvent_t  ev_fork = 0, ev_join = 0;
    if (s_side == 0) {
        cudaStreamCreateWithFlags(&s_side, cudaStreamNonBlocking);
        cudaEventCreateWithFlags(&ev_fork, cudaEventDisableTiming);
        cudaEventCreateWithFlags(&ev_join, cudaEventDisableTiming);
    }

    float* p_hcat; cudaGetSymbolAddress((void**)&p_hcat, g_hcat);

    /* fork: build_edges (DRAM-bound) runs parallel to the GEMM chain */
    cudaEventRecord(ev_fork, 0);
    cudaStreamWaitEvent(s_side, ev_fork, 0);
    build_edges<<<N_NODES, 256, 0, s_side>>>(adj);
    cudaEventRecord(ev_join, s_side);

    pack_W<<<NFEAT * DHID / 256, 256>>>(Ws);
    prep_v2<<<32, 256>>>(W_out, a_out);
    {
        dim3 grid(NHEADS, N_NODES / 128);
        sgemm1<<<grid, 256>>>(x, a_heads);
    }

    /* join before agg1 (needs edge lists + Wh + f-scores) */
    cudaStreamWaitEvent(0, ev_join, 0);
    agg1<<<N_NODES, 256>>>();
    {
        dim3 grid((NCLASS + 63) / 64, N_NODES / 128);
        sgemm2<<<grid, 256>>>(p_hcat, W_out);
    }
    agg2<<<N_NODES, 128>>>(out);
}